// round 2
// baseline (speedup 1.0000x reference)
#include <cuda_runtime.h>

#define NB 8
#define CC 64
#define TT 256
#define VQ 90
#define VK 50
#define SS 4
#define LAG 4
#define NLAG (LAG + 1)
#define TQ (TT - LAG)                 // 252
#define COLS_Q (TQ * VQ)              // 22680
#define COLS_T (TT * VQ)              // 23040
#define COLS_K (TT * VK)              // 12800
#define BN_EPS 1e-5f

// ---------------- scratch (static device memory; no allocations) ----------------
__device__ float g_q   [NB * SS * CC * COLS_Q];   // [n][s*C+c][t*VQ+vq], t<TQ
__device__ float g_k   [NB * SS * CC * COLS_K];   // [n][s*C+c][t*VK+vk]
__device__ float g_v   [NB * CC * COLS_K];        // [n][c][t*VK+vk]
__device__ float g_y   [NB * SS * CC * COLS_T];   // [n][s*C+c][t*VQ+vq]
__device__ float g_o1  [NB * CC * COLS_T];        // pre-BN out path
__device__ float g_d   [NB * CC * COLS_T];        // pre-BN down path
__device__ float g_att5[NLAG * NB * SS * VQ * VK];
__device__ float g_att [NB * SS * VQ * VK];
__device__ float g_stats[2 * CC * 2];             // [which][co][{mean, invstd}]

// ---------------- zero kernel ----------------
__global__ void zero_kernel(float* p, int n) {
    int i = blockIdx.x * blockDim.x + threadIdx.x;
    if (i < n) p[i] = 0.f;
}

// ---------------- generic conv1x1 GEMM: O[n][r][col] = sum_k W[r][k] X[n][k][col] + b[r] ----------------
__global__ __launch_bounds__(256) void gemm_bias(
    const float* __restrict__ W, const float* __restrict__ bias,
    const float* __restrict__ X, float* __restrict__ O,
    int K, int cols, int rsB, long bsB, long bsC)
{
    __shared__ float Ws[64][65];
    __shared__ float Xs[64][65];
    int tid = threadIdx.x;
    int tx = tid & 15, ty = tid >> 4;
    int n = blockIdx.z;
    int row0 = blockIdx.y * 64;
    int col0 = blockIdx.x * 64;
    const float* Xn = X + (long)n * bsB;
    float acc[4][4];
#pragma unroll
    for (int i = 0; i < 4; i++)
#pragma unroll
        for (int j = 0; j < 4; j++) acc[i][j] = 0.f;

    for (int kc = 0; kc < K; kc += 64) {
        for (int idx = tid; idx < 64 * 64; idx += 256) {
            int r = idx >> 6, k = idx & 63;
            Ws[r][k] = W[(long)(row0 + r) * K + kc + k];
        }
        for (int idx = tid; idx < 64 * 64; idx += 256) {
            int k = idx >> 6, c = idx & 63;
            int col = col0 + c;
            Xs[k][c] = (col < cols) ? Xn[(long)(kc + k) * rsB + col] : 0.f;
        }
        __syncthreads();
#pragma unroll 8
        for (int k = 0; k < 64; k++) {
            float a[4], b[4];
#pragma unroll
            for (int i = 0; i < 4; i++) a[i] = Ws[ty * 4 + i][k];
#pragma unroll
            for (int j = 0; j < 4; j++) b[j] = Xs[k][tx * 4 + j];
#pragma unroll
            for (int i = 0; i < 4; i++)
#pragma unroll
                for (int j = 0; j < 4; j++) acc[i][j] += a[i] * b[j];
        }
        __syncthreads();
    }
#pragma unroll
    for (int i = 0; i < 4; i++) {
        int r = row0 + ty * 4 + i;
        float bv = bias[r];
#pragma unroll
        for (int j = 0; j < 4; j++) {
            int col = col0 + tx * 4 + j;
            if (col < cols)
                O[(long)n * bsC + (long)r * cols + col] = acc[i][j] + bv;
        }
    }
}

// ---------------- 5-lag attention scores ----------------
// att5[l][n][s][vq][vk] += sum_{c in chunk, t<TQ} q[n,s,c,t,vq] * k[n,s,c,t+l,vk]
__global__ __launch_bounds__(512) void scores_kernel(
    const float* __restrict__ q, const float* __restrict__ k,
    float* __restrict__ att5)
{
    __shared__ float q_s[28][90];
    __shared__ float k_s[32][52];
    int tid = threadIdx.x;
    int ns = blockIdx.x;              // n*S+s
    int n = ns >> 2, s = ns & 3;
    int c0 = blockIdx.y * 4;          // 16 chunks of 4 channels
    int gq = tid % 30, gk = tid / 30; // gk<17 valid
    int vq0 = gq * 3, vk0 = gk * 3;
    bool active = tid < 510;

    float acc[NLAG][3][3];
#pragma unroll
    for (int l = 0; l < NLAG; l++)
#pragma unroll
        for (int i = 0; i < 3; i++)
#pragma unroll
            for (int j = 0; j < 3; j++) acc[l][i][j] = 0.f;

    for (int cc = 0; cc < 4; cc++) {
        int sc = s * CC + c0 + cc;
        const float* qrow = q + (long)(n * SS * CC + sc) * COLS_Q;
        const float* krow = k + (long)(n * SS * CC + sc) * COLS_K;
        for (int tt = 0; tt < 9; tt++) {
            int tbase = tt * 28;
            for (int idx = tid; idx < 28 * 90; idx += 512) {
                int i = idx / 90, vq = idx % 90;
                q_s[i][vq] = qrow[(tbase + i) * VQ + vq];
            }
            for (int idx = tid; idx < 32 * 52; idx += 512) {
                int i = idx / 52, vk = idx % 52;
                k_s[i][vk] = (vk < VK) ? krow[(tbase + i) * VK + vk] : 0.f;
            }
            __syncthreads();
            if (active) {
                float kw[3][5];
#pragma unroll
                for (int j = 0; j < 3; j++)
#pragma unroll
                    for (int l = 0; l < 4; l++) kw[j][l] = k_s[l][vk0 + j];
#pragma unroll 4
                for (int t = 0; t < 28; t++) {
#pragma unroll
                    for (int j = 0; j < 3; j++) kw[j][4] = k_s[t + 4][vk0 + j];
                    float qv[3];
#pragma unroll
                    for (int i = 0; i < 3; i++) qv[i] = q_s[t][vq0 + i];
#pragma unroll
                    for (int l = 0; l < NLAG; l++)
#pragma unroll
                        for (int i = 0; i < 3; i++)
#pragma unroll
                            for (int j = 0; j < 3; j++)
                                acc[l][i][j] += qv[i] * kw[j][l];
#pragma unroll
                    for (int j = 0; j < 3; j++)
#pragma unroll
                        for (int l = 0; l < 4; l++) kw[j][l] = kw[j][l + 1];
                }
            }
            __syncthreads();
        }
    }
    if (active) {
#pragma unroll
        for (int l = 0; l < NLAG; l++)
#pragma unroll
            for (int i = 0; i < 3; i++)
#pragma unroll
                for (int j = 0; j < 3; j++) {
                    int vk = vk0 + j;
                    if (vk < VK)
                        atomicAdd(&att5[(((long)(l * NB + n) * SS + s) * VQ + vq0 + i) * VK + vk],
                                  acc[l][i][j]);
                }
    }
}

// ---------------- (max+mean)/2 over lags, /scale, softmax over vk ----------------
__global__ void softmax_kernel(const float* __restrict__ att5, float* __restrict__ att)
{
    int r = blockIdx.x;               // (n*S+s)*VQ+vq, 2880 rows
    int tid = threadIdx.x;            // 64
    __shared__ float red[64];
    const float halfInv = 0.5f / sqrtf((float)(CC * TQ));
    float p = -1e30f;
    if (tid < VK) {
        float mx = -1e30f, sm = 0.f;
#pragma unroll
        for (int l = 0; l < NLAG; l++) {
            float v = att5[((long)l * (NB * SS * VQ) + r) * VK + tid];
            mx = fmaxf(mx, v);
            sm += v;
        }
        p = (mx + sm * 0.2f) * halfInv;
    }
    red[tid] = p;
    __syncthreads();
    for (int o = 32; o > 0; o >>= 1) {
        if (tid < o) red[tid] = fmaxf(red[tid], red[tid + o]);
        __syncthreads();
    }
    float m = red[0];
    __syncthreads();
    float e = (tid < VK) ? expf(p - m) : 0.f;
    red[tid] = e;
    __syncthreads();
    for (int o = 32; o > 0; o >>= 1) {
        if (tid < o) red[tid] += red[tid + o];
        __syncthreads();
    }
    if (tid < VK) att[(long)r * VK + tid] = e / red[0];
}

// ---------------- y[n,s,c,t,vq] = sum_vk att[n,s,vq,vk] * v[n,c,t,vk] ----------------
__global__ __launch_bounds__(256) void ygemm_kernel(
    const float* __restrict__ att, const float* __restrict__ v,
    float* __restrict__ y)
{
    __shared__ float att_s[96][51];
    __shared__ float v_s[64][51];
    int tid = threadIdx.x;
    int tx = tid & 15, ty = tid >> 4;
    int ns = blockIdx.y;              // n*S+s
    int n = ns >> 2;
    int ct0 = blockIdx.x * 64;        // ct = c*T + t in [0, 16384)

    for (int idx = tid; idx < 96 * 51; idx += 256)
        (&att_s[0][0])[idx] = 0.f;
    __syncthreads();
    for (int idx = tid; idx < VQ * VK; idx += 256) {
        int vq = idx / VK, vk = idx % VK;
        att_s[vq][vk] = att[((long)ns * VQ + vq) * VK + vk];
    }
    const float* vb = v + (long)n * CC * COLS_K + (long)ct0 * VK;
    for (int idx = tid; idx < 64 * VK; idx += 256)
        v_s[idx / VK][idx % VK] = vb[idx];
    __syncthreads();

    float acc[4][6];
#pragma unroll
    for (int i = 0; i < 4; i++)
#pragma unroll
        for (int j = 0; j < 6; j++) acc[i][j] = 0.f;

#pragma unroll 5
    for (int vk = 0; vk < VK; vk++) {
        float a[4], b[6];
#pragma unroll
        for (int i = 0; i < 4; i++) a[i] = v_s[ty * 4 + i][vk];
#pragma unroll
        for (int j = 0; j < 6; j++) b[j] = att_s[tx * 6 + j][vk];
#pragma unroll
        for (int i = 0; i < 4; i++)
#pragma unroll
            for (int j = 0; j < 6; j++) acc[i][j] += a[i] * b[j];
    }
    long ybase = (long)ns * (CC * TT * VQ);
#pragma unroll
    for (int i = 0; i < 4; i++) {
        long ct = ct0 + ty * 4 + i;
#pragma unroll
        for (int j = 0; j < 6; j++) {
            int vq = tx * 6 + j;
            if (vq < VQ) y[ybase + ct * VQ + vq] = acc[i][j];
        }
    }
}

// ---------------- per-channel BN stats (training mode, biased var) ----------------
__global__ void stats_kernel(const float* __restrict__ o1, const float* __restrict__ d,
                             float* __restrict__ stats)
{
    int co = blockIdx.x;
    int which = blockIdx.y;           // 0 = o1, 1 = d
    const float* src = which ? d : o1;
    int tid = threadIdx.x;            // 256
    float sum = 0.f, sq = 0.f;
    for (int idx = tid; idx < NB * COLS_T; idx += 256) {
        int n = idx / COLS_T, col = idx % COLS_T;
        float x = src[((long)n * CC + co) * COLS_T + col];
        sum += x;
        sq += x * x;
    }
    __shared__ float s1[256], s2[256];
    s1[tid] = sum; s2[tid] = sq;
    __syncthreads();
    for (int o = 128; o > 0; o >>= 1) {
        if (tid < o) { s1[tid] += s1[tid + o]; s2[tid] += s2[tid + o]; }
        __syncthreads();
    }
    if (tid == 0) {
        float M = (float)(NB * COLS_T);
        float mean = s1[0] / M;
        float var = s2[0] / M - mean * mean;
        stats[(which * CC + co) * 2 + 0] = mean;
        stats[(which * CC + co) * 2 + 1] = rsqrtf(var + BN_EPS);
    }
}

// ---------------- BN both paths + add + leaky relu ----------------
__global__ void final_kernel(const float* __restrict__ o1, const float* __restrict__ d,
                             const float* __restrict__ stats,
                             const float* __restrict__ gout, const float* __restrict__ bout,
                             const float* __restrict__ gdown, const float* __restrict__ bdown,
                             float* __restrict__ out)
{
    long idx = (long)blockIdx.x * blockDim.x + threadIdx.x;
    long total = (long)NB * CC * COLS_T;
    if (idx >= total) return;
    int co = (int)((idx / COLS_T) % CC);
    float mo = stats[co * 2 + 0], iso = stats[co * 2 + 1];
    float md = stats[(CC + co) * 2 + 0], isd = stats[(CC + co) * 2 + 1];
    float yv = (o1[idx] - mo) * iso * gout[co] + bout[co];
    float dv = (d[idx] - md) * isd * gdown[co] + bdown[co];
    float s = yv + dv;
    out[idx] = s > 0.f ? s : 0.1f * s;
}

// ---------------- launch ----------------
extern "C" void kernel_launch(void* const* d_in, const int* in_sizes, int n_in,
                              void* d_out, int out_size)
{
    const float* x_q   = (const float*)d_in[0];
    const float* x_k   = (const float*)d_in[1];
    const float* x_v   = (const float*)d_in[2];
    const float* Wq    = (const float*)d_in[3];
    const float* bq    = (const float*)d_in[4];
    const float* Wk    = (const float*)d_in[5];
    const float* bk    = (const float*)d_in[6];
    const float* Wv    = (const float*)d_in[7];
    const float* bv    = (const float*)d_in[8];
    const float* Wout  = (const float*)d_in[9];
    const float* bout  = (const float*)d_in[10];
    const float* g_out = (const float*)d_in[11];
    const float* b_out = (const float*)d_in[12];
    const float* Wdown = (const float*)d_in[13];
    const float* bdown = (const float*)d_in[14];
    const float* g_dn  = (const float*)d_in[15];
    const float* b_dn  = (const float*)d_in[16];

    float *q, *k, *v, *y, *o1, *db, *att5, *att, *stats;
    cudaGetSymbolAddress((void**)&q,     g_q);
    cudaGetSymbolAddress((void**)&k,     g_k);
    cudaGetSymbolAddress((void**)&v,     g_v);
    cudaGetSymbolAddress((void**)&y,     g_y);
    cudaGetSymbolAddress((void**)&o1,    g_o1);
    cudaGetSymbolAddress((void**)&db,    g_d);
    cudaGetSymbolAddress((void**)&att5,  g_att5);
    cudaGetSymbolAddress((void**)&att,   g_att);
    cudaGetSymbolAddress((void**)&stats, g_stats);

    int natt5 = NLAG * NB * SS * VQ * VK;
    zero_kernel<<<(natt5 + 255) / 256, 256>>>(att5, natt5);

    // projections
    gemm_bias<<<dim3((COLS_Q + 63) / 64, (SS * CC) / 64, NB), 256>>>(
        Wq, bq, x_q, q, CC, COLS_Q, COLS_T, (long)CC * COLS_T, (long)SS * CC * COLS_Q);
    gemm_bias<<<dim3((COLS_K + 63) / 64, (SS * CC) / 64, NB), 256>>>(
        Wk, bk, x_k, k, CC, COLS_K, COLS_K, (long)CC * COLS_K, (long)SS * CC * COLS_K);
    gemm_bias<<<dim3((COLS_K + 63) / 64, 1, NB), 256>>>(
        Wv, bv, x_v, v, CC, COLS_K, COLS_K, (long)CC * COLS_K, (long)CC * COLS_K);

    // multi-lag scores + softmax
    scores_kernel<<<dim3(NB * SS, 16), 512>>>(q, k, att5);
    softmax_kernel<<<NB * SS * VQ, 64>>>(att5, att);

    // y = att @ v
    ygemm_kernel<<<dim3((CC * TT) / 64, NB * SS), 256>>>(att, v, y);

    // output / downsample projections
    gemm_bias<<<dim3((COLS_T + 63) / 64, 1, NB), 256>>>(
        Wout, bout, y, o1, SS * CC, COLS_T, COLS_T, (long)SS * CC * COLS_T, (long)CC * COLS_T);
    gemm_bias<<<dim3((COLS_T + 63) / 64, 1, NB), 256>>>(
        Wdown, bdown, x_q, db, CC, COLS_T, COLS_T, (long)CC * COLS_T, (long)CC * COLS_T);

    // BN stats + fused epilogue
    stats_kernel<<<dim3(CC, 2), 256>>>(o1, db, stats);
    long total = (long)NB * CC * COLS_T;
    final_kernel<<<(unsigned)((total + 255) / 256), 256>>>(
        o1, db, stats, g_out, b_out, g_dn, b_dn, (float*)d_out);
}